// round 16
// baseline (speedup 1.0000x reference)
#include <cuda_runtime.h>
#include <cuda_fp16.h>
#include <math.h>
#include <stdint.h>

#define D_MODEL 1024
#define NHEAD   16
#define HEAD_DIM 64
#define BATCH   2
#define SEQ     2048
#define MTOT    (BATCH*SEQ)          // 4096

// ---------------- scratch (no allocations allowed) ----------------
__device__ __half g_qh[MTOT*D_MODEL];     // Q proj (half) -> rope in-place
__device__ __half g_kh[MTOT*D_MODEL];
__device__ __half g_vth[D_MODEL*MTOT];    // V proj TRANSPOSED [d][m], half
__device__ __half g_ctxh[MTOT*D_MODEL];   // attention out, half
__device__ __half g_xh [MTOT*D_MODEL];    // x -> half
__device__ __half g_wqh[D_MODEL*D_MODEL];
__device__ __half g_wkh[D_MODEL*D_MODEL];
__device__ __half g_wvh[D_MODEL*D_MODEL];
__device__ __half g_woh[D_MODEL*D_MODEL];

// ---------------- helpers ----------------
__device__ __forceinline__ uint32_t pk2(float a, float b) {
    __half2 h = __floats2half2_rn(a, b);
    return *(uint32_t*)&h;
}

__device__ __forceinline__ void mma16(float4& d, const uint32_t a[4],
                                      uint32_t b0, uint32_t b1) {
    asm volatile(
        "mma.sync.aligned.m16n8k16.row.col.f32.f16.f16.f32 "
        "{%0,%1,%2,%3},{%4,%5,%6,%7},{%8,%9},{%0,%1,%2,%3};"
        : "+f"(d.x), "+f"(d.y), "+f"(d.z), "+f"(d.w)
        : "r"(a[0]), "r"(a[1]), "r"(a[2]), "r"(a[3]), "r"(b0), "r"(b1));
}

__device__ __forceinline__ void ldsm4(uint32_t& r0, uint32_t& r1,
                                      uint32_t& r2, uint32_t& r3, uint32_t addr) {
    asm volatile("ldmatrix.sync.aligned.m8n8.x4.shared.b16 {%0,%1,%2,%3}, [%4];"
                 : "=r"(r0), "=r"(r1), "=r"(r2), "=r"(r3) : "r"(addr));
}

__device__ __forceinline__ void cpa16(uint32_t dst_smem, const void* src) {
    asm volatile("cp.async.cg.shared.global [%0], [%1], 16;"
                 :: "r"(dst_smem), "l"(src));
}
#define CPA_COMMIT() asm volatile("cp.async.commit_group;" ::: "memory")
#define CPA_WAIT(n)  asm volatile("cp.async.wait_group %0;" :: "n"(n) : "memory")

// =================================================================
// Convert x and the four weight matrices to fp16 (rn) once.
// =================================================================
__global__ void tohalf_kernel(const float* __restrict__ x,
                              const float* __restrict__ Wq,
                              const float* __restrict__ Wk,
                              const float* __restrict__ Wv,
                              const float* __restrict__ Wo)
{
    int i = blockIdx.x * blockDim.x + threadIdx.x;   // float4 index
    const int NX = MTOT * D_MODEL / 4;
    const int NW = D_MODEL * D_MODEL / 4;
    if (i < NX) {
        float4 v = ((const float4*)x)[i];
        ((uint2*)g_xh)[i] = make_uint2(pk2(v.x, v.y), pk2(v.z, v.w));
    }
    if (i < NW) {
        float4 v = ((const float4*)Wq)[i];
        ((uint2*)g_wqh)[i] = make_uint2(pk2(v.x, v.y), pk2(v.z, v.w));
        v = ((const float4*)Wk)[i];
        ((uint2*)g_wkh)[i] = make_uint2(pk2(v.x, v.y), pk2(v.z, v.w));
        v = ((const float4*)Wv)[i];
        ((uint2*)g_wvh)[i] = make_uint2(pk2(v.x, v.y), pk2(v.z, v.w));
        v = ((const float4*)Wo)[i];
        ((uint2*)g_woh)[i] = make_uint2(pk2(v.x, v.y), pk2(v.z, v.w));
    }
}

// =================================================================
// fp16 GEMM (fused over gridDim.z), BK=64, 3-stage cp.async ring,
// ONE barrier per k-iter (16 iters).  C = A @ W^T + b, f32 accum.
// halfout: z<2 outputs written half (Q/K proj); else f32 (O proj).
// z==2 (V projection): epilogue writes half TRANSPOSED to C2t[d][m].
// =================================================================
#define GSH 72   // smem row stride (halves): 64 data + 8 pad
#define GEMM_BUF (128 * GSH)                    // halves per tile buffer
#define GEMM_SMEM_BYTES (6 * GEMM_BUF * 2)      // 3xA + 3xB = 110592

__global__ __launch_bounds__(256, 2)
void gemm3_f16(const __half* __restrict__ A,
               const __half* __restrict__ W0, const __half* __restrict__ W1,
               const __half* __restrict__ W2,
               const float* __restrict__ B0, const float* __restrict__ B1,
               const float* __restrict__ B2,
               float* __restrict__ C0f,
               __half* __restrict__ H0, __half* __restrict__ H1,
               __half* __restrict__ C2t,
               int halfout, int M, int N, int K)
{
    extern __shared__ __half gsm[];

    const int z = blockIdx.z;
    const __half* W   = (z == 0) ? W0 : (z == 1) ? W1 : W2;
    const float* bias = (z == 0) ? B0 : (z == 1) ? B1 : B2;

    const int tid  = threadIdx.x;
    const int lane = tid & 31;
    const int warp = tid >> 5;
    const int wm   = warp >> 2;
    const int wn   = warp & 3;
    const int m0   = blockIdx.y * 128;
    const int n0   = blockIdx.x * 128;

    // cp.async: 64 halves/row = 8 chunks of 8; 32 row-threads
    const int srow  = tid >> 3;          // 0..31 (+32,+64,+96)
    const int schk  = (tid & 7) * 8;     // halves 0..56

    const int aRow = lane & 15;
    const int aChk = (lane >> 4) * 8;
    const int bRow = (lane & 7) + ((lane >> 4) * 8);
    const int bChk = ((lane >> 3) & 1) * 8;

    uint32_t sAu[3], sBu[3];
    #pragma unroll
    for (int i = 0; i < 3; i++) {
        sAu[i] = (uint32_t)__cvta_generic_to_shared(gsm + i * GEMM_BUF);
        sBu[i] = (uint32_t)__cvta_generic_to_shared(gsm + (3 + i) * GEMM_BUF);
    }

    const int nIter = K / 64;            // 16

    // preload k-iters 0 and 1
    #pragma unroll
    for (int t = 0; t < 2; t++) {
        int k0 = t * 64;
        #pragma unroll
        for (int i = 0; i < 4; i++) {
            int row = srow + i * 32;
            cpa16(sAu[t] + 2u * (row * GSH + schk),
                  &A[(size_t)(m0 + row) * K + k0 + schk]);
            cpa16(sBu[t] + 2u * (row * GSH + schk),
                  &W[(size_t)(n0 + row) * K + k0 + schk]);
        }
        CPA_COMMIT();
    }

    float4 acc[4][4] = {};
    int cur = 0, nxt2 = 2;               // ring slots: it%3, (it+2)%3

    for (int it = 0; it < nIter; it++) {
        CPA_WAIT(1);
        __syncthreads();                 // tile it visible; slot nxt2 free

        if (it + 2 < nIter) {
            int k0 = (it + 2) * 64;
            #pragma unroll
            for (int i = 0; i < 4; i++) {
                int row = srow + i * 32;
                cpa16(sAu[nxt2] + 2u * (row * GSH + schk),
                      &A[(size_t)(m0 + row) * K + k0 + schk]);
                cpa16(sBu[nxt2] + 2u * (row * GSH + schk),
                      &W[(size_t)(n0 + row) * K + k0 + schk]);
            }
        }
        CPA_COMMIT();

        const uint32_t cAu = sAu[cur];
        const uint32_t cBu = sBu[cur];

        #pragma unroll
        for (int ks = 0; ks < 4; ks++) {
            int kk = ks * 16;
            uint32_t af[4][4], bf[4][2];
            #pragma unroll
            for (int mt = 0; mt < 4; mt++)
                ldsm4(af[mt][0], af[mt][1], af[mt][2], af[mt][3],
                      cAu + 2u * ((wm * 64 + mt * 16 + aRow) * GSH + kk + aChk));
            #pragma unroll
            for (int t = 0; t < 2; t++)
                ldsm4(bf[2*t][0], bf[2*t][1], bf[2*t+1][0], bf[2*t+1][1],
                      cBu + 2u * ((wn * 32 + t * 16 + bRow) * GSH + kk + bChk));
            #pragma unroll
            for (int mt = 0; mt < 4; mt++)
                #pragma unroll
                for (int nt = 0; nt < 4; nt++)
                    mma16(acc[mt][nt], af[mt], bf[nt][0], bf[nt][1]);
        }

        cur  = (cur  == 2) ? 0 : cur  + 1;
        nxt2 = (nxt2 == 2) ? 0 : nxt2 + 1;
    }

    if (z == 2) {
        #pragma unroll
        for (int nt = 0; nt < 4; nt++) {
            int col = n0 + wn * 32 + nt * 8 + 2 * (lane & 3);
            float2 bz = *(const float2*)&bias[col];
            #pragma unroll
            for (int mt = 0; mt < 4; mt++) {
                int row = m0 + wm * 64 + mt * 16 + (lane >> 2);
                C2t[(size_t) col      * M + row    ] = __float2half_rn(acc[mt][nt].x + bz.x);
                C2t[(size_t)(col + 1) * M + row    ] = __float2half_rn(acc[mt][nt].y + bz.y);
                C2t[(size_t) col      * M + row + 8] = __float2half_rn(acc[mt][nt].z + bz.x);
                C2t[(size_t)(col + 1) * M + row + 8] = __float2half_rn(acc[mt][nt].w + bz.y);
            }
        }
    } else if (halfout) {
        __half* H = (z == 0) ? H0 : H1;
        #pragma unroll
        for (int nt = 0; nt < 4; nt++) {
            int col = n0 + wn * 32 + nt * 8 + 2 * (lane & 3);
            float2 bz = *(const float2*)&bias[col];
            #pragma unroll
            for (int mt = 0; mt < 4; mt++) {
                int row = m0 + wm * 64 + mt * 16 + (lane >> 2);
                *(uint32_t*)&H[(size_t)row * N + col] =
                    pk2(acc[mt][nt].x + bz.x, acc[mt][nt].y + bz.y);
                *(uint32_t*)&H[(size_t)(row + 8) * N + col] =
                    pk2(acc[mt][nt].z + bz.x, acc[mt][nt].w + bz.y);
            }
        }
    } else {
        #pragma unroll
        for (int nt = 0; nt < 4; nt++) {
            int col = n0 + wn * 32 + nt * 8 + 2 * (lane & 3);
            float2 bz = *(const float2*)&bias[col];
            #pragma unroll
            for (int mt = 0; mt < 4; mt++) {
                int row = m0 + wm * 64 + mt * 16 + (lane >> 2);
                float2 v0 = { acc[mt][nt].x + bz.x, acc[mt][nt].y + bz.y };
                float2 v1 = { acc[mt][nt].z + bz.x, acc[mt][nt].w + bz.y };
                *(float2*)&C0f[(size_t)row * N + col]       = v0;
                *(float2*)&C0f[(size_t)(row + 8) * N + col] = v1;
            }
        }
    }
}

// =================================================================
// RoPE (in-place on half Q and K).
// =================================================================
__global__ void rope_kernel(__half* __restrict__ q, __half* __restrict__ k,
                            const float* __restrict__ cosp,
                            const float* __restrict__ sinp)
{
    int idx = blockIdx.x * blockDim.x + threadIdx.x;
    int d  = idx & 31;
    int h  = (idx >> 5) & (NHEAD - 1);
    int bs = idx >> 9;
    int s  = bs & (SEQ - 1);

    int base = bs * D_MODEL + h * HEAD_DIM + d;
    float c1 = cosp[s * HEAD_DIM + d];
    float s1 = sinp[s * HEAD_DIM + d];
    float c2 = cosp[s * HEAD_DIM + d + 32];
    float s2 = sinp[s * HEAD_DIM + d + 32];

    float q1 = __half2float(q[base]), q2 = __half2float(q[base + 32]);
    q[base]      = __float2half_rn(q1 * c1 - q2 * s1);
    q[base + 32] = __float2half_rn(q2 * c2 + q1 * s2);

    float k1 = __half2float(k[base]), k2 = __half2float(k[base + 32]);
    k[base]      = __float2half_rn(k1 * c1 - k2 * s1);
    k[base + 32] = __float2half_rn(k2 * c2 + k1 * s2);
}

// =================================================================
// Flash attention, fp16 m16n8k16 (R14 structure): Q frags + P in
// registers, 3-stage cp.async K/V ring, ONE barrier per KV tile.
// CTA = 128 q-rows of one (b,h), 256 threads (8 warps).
// =================================================================
#define PS 72                                   // smem row stride (halves)
#define NT_KV (SEQ / 64)                        // 32 tiles
#define KV_BUF (64 * PS)                        // halves per K or V buffer
#define ATTN_SMEM_HALVES (6 * KV_BUF + 128 * PS)
#define ATTN_SMEM_BYTES  (ATTN_SMEM_HALVES * 2) // 73728

__global__ __launch_bounds__(256, 2)
void attn_f16(const __half* __restrict__ Q, const __half* __restrict__ K,
              const __half* __restrict__ Vt, __half* __restrict__ O)
{
    extern __shared__ __half smh[];
    __half* sQs = smh + 6 * KV_BUF;

    const int b    = blockIdx.z;
    const int h    = blockIdx.y;
    const int qt   = blockIdx.x;
    const int tid  = threadIdx.x;
    const int lane = tid & 31;
    const int warp = tid >> 5;

    const int srow = tid >> 3;             // 0..31 (+32 second)
    const int schk = (tid & 7) * 8;        // halves 0..56

    const int qRow = warp * 16 + (lane & 15);
    const int qChk = (lane >> 4) * 8;
    const int kRow = (lane & 7) + ((lane >> 4) * 8);
    const int kChk = ((lane >> 3) & 1) * 8;

    uint32_t sKu[3], sVu[3];
    #pragma unroll
    for (int i = 0; i < 3; i++) {
        sKu[i] = (uint32_t)__cvta_generic_to_shared(smh + i * KV_BUF);
        sVu[i] = (uint32_t)__cvta_generic_to_shared(smh + (3 + i) * KV_BUF);
    }
    const uint32_t sQu = (uint32_t)__cvta_generic_to_shared(sQs);

    const __half* Qb  = Q  + ((size_t)(b * SEQ + qt * 128) * D_MODEL + h * 64);
    const __half* Kb  = K  + ((size_t)(b * SEQ) * D_MODEL + h * 64);
    const __half* Vtb = Vt + ((size_t)(h * 64) * MTOT + b * SEQ);

    // ---- issue cp.async for tiles 0 and 1 ----
    #pragma unroll
    for (int t = 0; t < 2; t++) {
        #pragma unroll
        for (int i = 0; i < 2; i++) {
            int row = srow + i * 32;
            cpa16(sKu[t] + 2u * (row * PS + schk),
                  &Kb [(size_t)(t * 64 + row) * D_MODEL + schk]);
            cpa16(sVu[t] + 2u * (row * PS + schk),
                  &Vtb[(size_t)row * MTOT + t * 64 + schk]);
        }
        CPA_COMMIT();
    }

    // ---- stage Q tile, hoist a-fragments into registers ----
    #pragma unroll
    for (int i = 0; i < 4; i++) {
        int f   = tid + i * 256;
        int row = f >> 3;
        int cc  = (f & 7) * 8;
        *(uint4*)&sQs[row * PS + cc] = *(const uint4*)&Qb[(size_t)row * D_MODEL + cc];
    }
    __syncthreads();
    uint32_t qf[4][4];
    #pragma unroll
    for (int ks = 0; ks < 4; ks++)
        ldsm4(qf[ks][0], qf[ks][1], qf[ks][2], qf[ks][3],
              sQu + 2u * (qRow * PS + ks * 16 + qChk));

    const float SC = 0.125f * 1.44269504088896340736f;  // 1/sqrt(64)*log2(e)

    float m0 = -1e30f, m1 = -1e30f, l0 = 0.f, l1 = 0.f;
    float4 oacc[8] = {};

    int cur = 0, nxt2 = 2;               // ring slots kt%3, (kt+2)%3

    for (int kt = 0; kt < NT_KV; kt++) {
        CPA_WAIT(1);
        __syncthreads();                 // tile kt visible; slot nxt2 free

        if (kt + 2 < NT_KV) {
            #pragma unroll
            for (int i = 0; i < 2; i++) {
                int row = srow + i * 32;
                cpa16(sKu[nxt2] + 2u * (row * PS + schk),
                      &Kb [(size_t)((kt + 2) * 64 + row) * D_MODEL + schk]);
                cpa16(sVu[nxt2] + 2u * (row * PS + schk),
                      &Vtb[(size_t)row * MTOT + (kt + 2) * 64 + schk]);
            }
        }
        CPA_COMMIT();

        const uint32_t cK = sKu[cur];
        const uint32_t cV = sVu[cur];

        // ---- scores = Q K^T ----
        float4 s[8] = {};
        #pragma unroll
        for (int ks = 0; ks < 4; ks++) {
            int kk = ks * 16;
            uint32_t bfr[8][2];
            #pragma unroll
            for (int t = 0; t < 4; t++)
                ldsm4(bfr[2*t][0], bfr[2*t][1], bfr[2*t+1][0], bfr[2*t+1][1],
                      cK + 2u * ((t * 16 + kRow) * PS + kk + kChk));
            #pragma unroll
            for (int nt = 0; nt < 8; nt++)
                mma16(s[nt], qf[ks], bfr[nt][0], bfr[nt][1]);
        }

        // ---- online softmax (base-2, scale folded into FFMA) ----
        float rm0 = -1e30f, rm1 = -1e30f;
        #pragma unroll
        for (int nt = 0; nt < 8; nt++) {
            rm0 = fmaxf(rm0, fmaxf(s[nt].x, s[nt].y));
            rm1 = fmaxf(rm1, fmaxf(s[nt].z, s[nt].w));
        }
        rm0 = fmaxf(rm0, __shfl_xor_sync(0xffffffff, rm0, 1));
        rm0 = fmaxf(rm0, __shfl_xor_sync(0xffffffff, rm0, 2));
        rm1 = fmaxf(rm1, __shfl_xor_sync(0xffffffff, rm1, 1));
        rm1 = fmaxf(rm1, __shfl_xor_sync(0xffffffff, rm1, 2));

        float mn0 = fmaxf(m0, rm0 * SC);
        float mn1 = fmaxf(m1, rm1 * SC);
        float al0 = exp2f(m0 - mn0);
        float al1 = exp2f(m1 - mn1);
        m0 = mn0; m1 = mn1;

        uint32_t p[8][2];
        float rs0 = 0.f, rs1 = 0.f;
        #pragma unroll
        for (int nt = 0; nt < 8; nt++) {
            float px = exp2f(fmaf(s[nt].x, SC, -mn0));
            float py = exp2f(fmaf(s[nt].y, SC, -mn0));
            float pz = exp2f(fmaf(s[nt].z, SC, -mn1));
            float pw = exp2f(fmaf(s[nt].w, SC, -mn1));
            rs0 += px + py;
            rs1 += pz + pw;
            p[nt][0] = pk2(px, py);
            p[nt][1] = pk2(pz, pw);
        }
        rs0 += __shfl_xor_sync(0xffffffff, rs0, 1);
        rs0 += __shfl_xor_sync(0xffffffff, rs0, 2);
        rs1 += __shfl_xor_sync(0xffffffff, rs1, 1);
        rs1 += __shfl_xor_sync(0xffffffff, rs1, 2);

        l0 = l0 * al0 + rs0;
        l1 = l1 * al1 + rs1;

        #pragma unroll
        for (int nt = 0; nt < 8; nt++) {
            oacc[nt].x *= al0; oacc[nt].y *= al0;
            oacc[nt].z *= al1; oacc[nt].w *= al1;
        }

        // ---- oacc += P @ V ----
        #pragma unroll
        for (int ks = 0; ks < 4; ks++) {
            int kk = ks * 16;
            uint32_t af[4] = { p[2*ks][0], p[2*ks][1], p[2*ks+1][0], p[2*ks+1][1] };
            uint32_t bfr[8][2];
            #pragma unroll
            for (int t = 0; t < 4; t++)
                ldsm4(bfr[2*t][0], bfr[2*t][1], bfr[2*t+1][0], bfr[2*t+1][1],
                      cV + 2u * ((t * 16 + kRow) * PS + kk + kChk));
            #pragma unroll
            for (int nt = 0; nt < 8; nt++)
                mma16(oacc[nt], af, bfr[nt][0], bfr[nt][1]);
        }

        cur  = (cur  == 2) ? 0 : cur  + 1;
        nxt2 = (nxt2 == 2) ? 0 : nxt2 + 1;
    }

    // ---- epilogue: normalize, write half ctx ----
    const int er = warp * 16 + (lane >> 2);
    float inv0 = 1.f / l0;
    float inv1 = 1.f / l1;
    __half* Ob = O + ((size_t)(b * SEQ + qt * 128) * D_MODEL + h * 64);
    #pragma unroll
    for (int nt = 0; nt < 8; nt++) {
        int col = nt * 8 + 2 * (lane & 3);
        *(uint32_t*)&Ob[(size_t) er      * D_MODEL + col] =
            pk2(oacc[nt].x * inv0, oacc[nt].y * inv0);
        *(uint32_t*)&Ob[(size_t)(er + 8) * D_MODEL + col] =
            pk2(oacc[nt].z * inv1, oacc[nt].w * inv1);
    }
}

// =================================================================
extern "C" void kernel_launch(void* const* d_in, const int* in_sizes, int n_in,
                              void* d_out, int out_size)
{
    const float* x    = (const float*)d_in[0];
    const float* cosp = (const float*)d_in[1];
    const float* sinp = (const float*)d_in[2];
    const float* Wq   = (const float*)d_in[3];
    const float* bq   = (const float*)d_in[4];
    const float* Wk   = (const float*)d_in[5];
    const float* bk   = (const float*)d_in[6];
    const float* Wv   = (const float*)d_in[7];
    const float* bv   = (const float*)d_in[8];
    const float* Wo   = (const float*)d_in[9];
    const float* bo   = (const float*)d_in[10];
    float* out = (float*)d_out;

    __half *qh, *kh, *vth, *ctxh, *xh, *wqh, *wkh, *wvh, *woh;
    cudaGetSymbolAddress((void**)&qh,   g_qh);
    cudaGetSymbolAddress((void**)&kh,   g_kh);
    cudaGetSymbolAddress((void**)&vth,  g_vth);
    cudaGetSymbolAddress((void**)&ctxh, g_ctxh);
    cudaGetSymbolAddress((void**)&xh,   g_xh);
    cudaGetSymbolAddress((void**)&wqh,  g_wqh);
    cudaGetSymbolAddress((void**)&wkh,  g_wkh);
    cudaGetSymbolAddress((void**)&wvh,  g_wvh);
    cudaGetSymbolAddress((void**)&woh,  g_woh);

    tohalf_kernel<<<(MTOT * D_MODEL / 4 + 255) / 256, 256>>>(x, Wq, Wk, Wv, Wo);

    cudaFuncSetAttribute(gemm3_f16,
                         cudaFuncAttributeMaxDynamicSharedMemorySize,
                         GEMM_SMEM_BYTES);
    dim3 g3(D_MODEL / 128, MTOT / 128, 3);   // (8, 32, 3)
    gemm3_f16<<<g3, 256, GEMM_SMEM_BYTES>>>(xh, wqh, wkh, wvh, bq, bk, bv,
                           (float*)nullptr, qh, kh, vth, 1,
                           MTOT, D_MODEL, D_MODEL);

    rope_kernel<<<(MTOT * NHEAD * 32) / 256, 256>>>(qh, kh, cosp, sinp);

    cudaFuncSetAttribute(attn_f16,
                         cudaFuncAttributeMaxDynamicSharedMemorySize,
                         ATTN_SMEM_BYTES);
    attn_f16<<<dim3(SEQ / 128, NHEAD, BATCH), 256, ATTN_SMEM_BYTES>>>(qh, kh, vth, ctxh);

    dim3 g1(D_MODEL / 128, MTOT / 128, 1);
    gemm3_f16<<<g1, 256, GEMM_SMEM_BYTES>>>(ctxh, woh, woh, woh, bo, bo, bo,
                           out, (__half*)nullptr, (__half*)nullptr, (__half*)nullptr, 0,
                           MTOT, D_MODEL, D_MODEL);
}